// round 2
// baseline (speedup 1.0000x reference)
#include <cuda_runtime.h>
#include <math.h>

#define NF       13776
#define KMAX     8
#define NBLOCKS  148
#define NTHREADS 256
#define NWARPS   (NBLOCKS * (NTHREADS / 32))   // 1184

// ---------------------------------------------------------------------------
// Scratch (__device__ globals — allocation-free)
// ---------------------------------------------------------------------------
__device__ float4 d_tri4[NF * 3];   // per-face vertices, one float4 per vertex (w=0)
__device__ float4 d_bbmin[NF];
__device__ float4 d_bbmax[NF];
__device__ int4   d_fidx[NF];       // 3 vertex ids per face (w unused)
__device__ float  d_part[NBLOCKS];
__device__ unsigned d_barArrive = 0;
__device__ unsigned d_barGen    = 0; // monotonic across graph replays — reusable barrier

// ---------------------------------------------------------------------------
// Grid-wide barrier (generation counter; safe across CUDA-graph replays).
// All NBLOCKS blocks are co-resident (1 block/SM, 148 <= SM count) so no
// deadlock. Every thread fences before arrival so phase-1 stores are visible.
// ---------------------------------------------------------------------------
__device__ __forceinline__ void grid_barrier() {
    __threadfence();
    __syncthreads();
    if (threadIdx.x == 0) {
        unsigned gen = *(volatile unsigned*)&d_barGen;
        unsigned t   = atomicAdd(&d_barArrive, 1u);
        if (t == NBLOCKS - 1) {
            atomicExch(&d_barArrive, 0u);
            __threadfence();
            atomicAdd(&d_barGen, 1u);
        } else {
            while (*(volatile unsigned*)&d_barGen == gen) { }
        }
        __threadfence();
    }
    __syncthreads();
}

// ---------------------------------------------------------------------------
// Cone-field penalty of src triangle (s0,s1,s2) at the 3 vertices p0..p2.
// SIGMA=0.5, PENALIZE_OUTSIDE, phi^2 form.
// ---------------------------------------------------------------------------
__device__ __forceinline__ float cone_pen(float4 s0, float4 s1, float4 s2,
                                          float4 p0, float4 p1, float4 p2) {
    float e0x = s1.x - s0.x, e0y = s1.y - s0.y, e0z = s1.z - s0.z;
    float e1x = s2.x - s0.x, e1y = s2.y - s0.y, e1z = s2.z - s0.z;
    float nx = e0y * e1z - e0z * e1y;
    float ny = e0z * e1x - e0x * e1z;
    float nz = e0x * e1y - e0y * e1x;
    float l  = sqrtf(nx * nx + ny * ny + nz * nz);
    float inv = 1.0f / (l + 1e-8f);
    nx *= inv; ny *= inv; nz *= inv;
    float cx = (s0.x + s1.x + s2.x) * (1.0f / 3.0f);
    float cy = (s0.y + s1.y + s2.y) * (1.0f / 3.0f);
    float cz = (s0.z + s1.z + s2.z) * (1.0f / 3.0f);
    float acc = 0.0f;
#pragma unroll
    for (int k = 0; k < 3; k++) {
        float4 p = (k == 0) ? p0 : ((k == 1) ? p1 : p2);
        float ux = p.x - cx, uy = p.y - cy, uz = p.z - cz;
        float h  = ux * nx + uy * ny + uz * nz;
        float wx = ux - h * nx, wy = uy - h * ny, wz = uz - h * nz;
        float r  = sqrtf(wx * wx + wy * wy + wz * wz);
        float radial = fmaxf(1.0f - 2.0f * r, 0.0f);
        float depth  = fmaxf(-h, 0.0f) + fmaxf(h, 0.0f) * expf(-2.0f * h);
        float phi = radial * depth;
        acc += phi * phi;
    }
    return acc;
}

// ---------------------------------------------------------------------------
// Single fused persistent kernel: prep -> barrier -> collide -> barrier -> reduce
// ---------------------------------------------------------------------------
__global__ __launch_bounds__(NTHREADS, 1)
void fused_kernel(const float* __restrict__ verts,
                  const int*  __restrict__ faces,
                  float* __restrict__ out) {
    const int tid  = threadIdx.x;
    const int lane = tid & 31;
    const int wid  = tid >> 5;

    // ---------------- Phase 1: gather + AABB ----------------
    {
        int f = blockIdx.x * NTHREADS + tid;   // grid covers NF in one pass
        if (f < NF) {
            int i0 = faces[3 * f + 0];
            int i1 = faces[3 * f + 1];
            int i2 = faces[3 * f + 2];
            float x0 = verts[3 * i0], y0 = verts[3 * i0 + 1], z0 = verts[3 * i0 + 2];
            float x1 = verts[3 * i1], y1 = verts[3 * i1 + 1], z1 = verts[3 * i1 + 2];
            float x2 = verts[3 * i2], y2 = verts[3 * i2 + 1], z2 = verts[3 * i2 + 2];
            d_tri4[3 * f + 0] = make_float4(x0, y0, z0, 0.f);
            d_tri4[3 * f + 1] = make_float4(x1, y1, z1, 0.f);
            d_tri4[3 * f + 2] = make_float4(x2, y2, z2, 0.f);
            d_fidx[f] = make_int4(i0, i1, i2, 0);
            d_bbmin[f] = make_float4(fminf(x0, fminf(x1, x2)),
                                     fminf(y0, fminf(y1, y2)),
                                     fminf(z0, fminf(z1, z2)), 0.f);
            d_bbmax[f] = make_float4(fmaxf(x0, fmaxf(x1, x2)),
                                     fmaxf(y0, fmaxf(y1, y2)),
                                     fmaxf(z0, fmaxf(z1, z2)), 0.f);
        }
    }

    grid_barrier();

    // ---------------- Phase 2: warp-per-face collide + penalty ----------------
    __shared__ float s_warp[NTHREADS / 32];
    float blockPen = 0.0f;  // only meaningful via s_warp path

    float pen = 0.0f;
    const int gwarp = blockIdx.x * (NTHREADS / 32) + wid;
    for (int f = gwarp; f < NF; f += NWARPS) {
        const float4 fmn = d_bbmin[f];
        const float4 fmx = d_bbmax[f];
        const int4   fid = d_fidx[f];

        int found = 0;
        int myIntr = -1;
        for (int base = 0; base < NF && found < KMAX; base += 32) {
            int j = base + lane;
            bool v = false;
            if (j < NF) {
                float4 jmn = d_bbmin[j];
                float4 jmx = d_bbmax[j];
                bool ov = (fmn.x <= jmx.x) & (jmn.x <= fmx.x)
                        & (fmn.y <= jmx.y) & (jmn.y <= fmx.y)
                        & (fmn.z <= jmx.z) & (jmn.z <= fmx.z);
                if (ov) {
                    int4 jid = d_fidx[j];
                    bool share = (jid.x == fid.x) | (jid.x == fid.y) | (jid.x == fid.z)
                               | (jid.y == fid.x) | (jid.y == fid.y) | (jid.y == fid.z)
                               | (jid.z == fid.x) | (jid.z == fid.y) | (jid.z == fid.z);
                    v = !share;
                }
            }
            unsigned m = __ballot_sync(0xffffffffu, v);
            while (m && found < KMAX) {
                int b = __ffs(m) - 1;
                if (lane == found) myIntr = base + b;
                found++;
                m &= (m - 1);
            }
        }

        if (lane < found) {
            float4 r0 = d_tri4[3 * f + 0];
            float4 r1 = d_tri4[3 * f + 1];
            float4 r2 = d_tri4[3 * f + 2];
            float4 i0 = d_tri4[3 * myIntr + 0];
            float4 i1 = d_tri4[3 * myIntr + 1];
            float4 i2 = d_tri4[3 * myIntr + 2];
            pen += cone_pen(r0, r1, r2, i0, i1, i2)
                 + cone_pen(i0, i1, i2, r0, r1, r2);
        }
    }

    // warp reduce (fixed order -> deterministic)
#pragma unroll
    for (int o = 16; o; o >>= 1)
        pen += __shfl_down_sync(0xffffffffu, pen, o);
    if (lane == 0) s_warp[wid] = pen;
    __syncthreads();
    if (tid == 0) {
        blockPen = 0.0f;
#pragma unroll
        for (int w = 0; w < NTHREADS / 32; w++) blockPen += s_warp[w];
        d_part[blockIdx.x] = blockPen;
    }

    grid_barrier();

    // ---------------- Phase 3: block 0 final deterministic reduce ----------------
    if (blockIdx.x == 0 && tid == 0) {
        float s = 0.0f;
#pragma unroll 4
        for (int i = 0; i < NBLOCKS; i++) s += d_part[i];
        out[0] = s;
    }
}

extern "C" void kernel_launch(void* const* d_in, const int* in_sizes, int n_in,
                              void* d_out, int out_size) {
    const float* verts = (const float*)d_in[0];  // [1,6890,3] float32
    const int*   faces = (const int*)d_in[1];    // [13776*3] int32
    (void)in_sizes; (void)n_in; (void)out_size;

    fused_kernel<<<NBLOCKS, NTHREADS>>>(verts, faces, (float*)d_out);
}

// round 3
// speedup vs baseline: 1.2094x; 1.2094x over previous
#include <cuda_runtime.h>
#include <math.h>

#define NF       13776
#define KMAX     8
#define NBLOCKS  148
#define NTHREADS 1024
#define WPB      (NTHREADS / 32)            // 32 warps per block
#define NWARPS   (NBLOCKS * WPB)            // 4736

// ---------------------------------------------------------------------------
// Scratch (__device__ globals — allocation-free)
// ---------------------------------------------------------------------------
__device__ float4 d_tri4[NF * 3];   // per-face vertices (w=0)
__device__ float4 d_aabb[NF * 2];   // [2f]=bbmin, [2f+1]=bbmax (adjacent -> 1 seg)
__device__ int4   d_fidx[NF];       // 3 vertex ids per face
__device__ float  d_part[NBLOCKS];
__device__ unsigned d_barArrive = 0;
__device__ unsigned d_barGen    = 0; // monotonic across graph replays

// ---------------------------------------------------------------------------
// Grid-wide barrier (generation counter; 148 co-resident blocks, 1/SM).
// ---------------------------------------------------------------------------
__device__ __forceinline__ void grid_barrier() {
    __threadfence();
    __syncthreads();
    if (threadIdx.x == 0) {
        unsigned gen = *(volatile unsigned*)&d_barGen;
        unsigned t   = atomicAdd(&d_barArrive, 1u);
        if (t == NBLOCKS - 1) {
            atomicExch(&d_barArrive, 0u);
            __threadfence();
            atomicAdd(&d_barGen, 1u);
        } else {
            while (*(volatile unsigned*)&d_barGen == gen) { }
        }
        __threadfence();
    }
    __syncthreads();
}

// ---------------------------------------------------------------------------
// Cone-field penalty (SIGMA=0.5, PENALIZE_OUTSIDE, phi^2 form).
// ---------------------------------------------------------------------------
__device__ __forceinline__ float cone_pen(float4 s0, float4 s1, float4 s2,
                                          float4 p0, float4 p1, float4 p2) {
    float e0x = s1.x - s0.x, e0y = s1.y - s0.y, e0z = s1.z - s0.z;
    float e1x = s2.x - s0.x, e1y = s2.y - s0.y, e1z = s2.z - s0.z;
    float nx = e0y * e1z - e0z * e1y;
    float ny = e0z * e1x - e0x * e1z;
    float nz = e0x * e1y - e0y * e1x;
    float l  = sqrtf(nx * nx + ny * ny + nz * nz);
    float inv = 1.0f / (l + 1e-8f);
    nx *= inv; ny *= inv; nz *= inv;
    float cx = (s0.x + s1.x + s2.x) * (1.0f / 3.0f);
    float cy = (s0.y + s1.y + s2.y) * (1.0f / 3.0f);
    float cz = (s0.z + s1.z + s2.z) * (1.0f / 3.0f);
    float acc = 0.0f;
#pragma unroll
    for (int k = 0; k < 3; k++) {
        float4 p = (k == 0) ? p0 : ((k == 1) ? p1 : p2);
        float ux = p.x - cx, uy = p.y - cy, uz = p.z - cz;
        float h  = ux * nx + uy * ny + uz * nz;
        float wx = ux - h * nx, wy = uy - h * ny, wz = uz - h * nz;
        float r  = sqrtf(wx * wx + wy * wy + wz * wz);
        float radial = fmaxf(1.0f - 2.0f * r, 0.0f);
        float depth  = fmaxf(-h, 0.0f) + fmaxf(h, 0.0f) * expf(-2.0f * h);
        float phi = radial * depth;
        acc += phi * phi;
    }
    return acc;
}

// ---------------------------------------------------------------------------
// Single fused kernel, 1024 threads/block for latency hiding.
// ---------------------------------------------------------------------------
__global__ __launch_bounds__(NTHREADS, 1)
void fused_kernel(const float* __restrict__ verts,
                  const int*  __restrict__ faces,
                  float* __restrict__ out) {
    const int tid  = threadIdx.x;
    const int lane = tid & 31;
    const int wid  = tid >> 5;

    // ---------------- Phase 1: gather + AABB (one face per thread) ----------
    for (int f = blockIdx.x * NTHREADS + tid; f < NF; f += NBLOCKS * NTHREADS) {
        int i0 = faces[3 * f + 0];
        int i1 = faces[3 * f + 1];
        int i2 = faces[3 * f + 2];
        float x0 = verts[3 * i0], y0 = verts[3 * i0 + 1], z0 = verts[3 * i0 + 2];
        float x1 = verts[3 * i1], y1 = verts[3 * i1 + 1], z1 = verts[3 * i1 + 2];
        float x2 = verts[3 * i2], y2 = verts[3 * i2 + 1], z2 = verts[3 * i2 + 2];
        d_tri4[3 * f + 0] = make_float4(x0, y0, z0, 0.f);
        d_tri4[3 * f + 1] = make_float4(x1, y1, z1, 0.f);
        d_tri4[3 * f + 2] = make_float4(x2, y2, z2, 0.f);
        d_fidx[f] = make_int4(i0, i1, i2, 0);
        d_aabb[2 * f + 0] = make_float4(fminf(x0, fminf(x1, x2)),
                                        fminf(y0, fminf(y1, y2)),
                                        fminf(z0, fminf(z1, z2)), 0.f);
        d_aabb[2 * f + 1] = make_float4(fmaxf(x0, fmaxf(x1, x2)),
                                        fmaxf(y0, fmaxf(y1, y2)),
                                        fmaxf(z0, fmaxf(z1, z2)), 0.f);
    }

    grid_barrier();

    // ---------------- Phase 2: warp-per-face collide + penalty --------------
    __shared__ float s_warp[WPB];

    float pen = 0.0f;
    const int gwarp = blockIdx.x * WPB + wid;
    for (int f = gwarp; f < NF; f += NWARPS) {
        const float4 fmn = d_aabb[2 * f + 0];
        const float4 fmx = d_aabb[2 * f + 1];
        const int4   fid = d_fidx[f];

        int found = 0;
        int myIntr = -1;
        for (int base = 0; base < NF && found < KMAX; base += 32) {
            int j = base + lane;
            bool v = false;
            if (j < NF) {
                float4 jmn = d_aabb[2 * j + 0];
                float4 jmx = d_aabb[2 * j + 1];
                bool ov = (fmn.x <= jmx.x) & (jmn.x <= fmx.x)
                        & (fmn.y <= jmx.y) & (jmn.y <= fmx.y)
                        & (fmn.z <= jmx.z) & (jmn.z <= fmx.z);
                if (ov) {
                    int4 jid = d_fidx[j];
                    bool share = (jid.x == fid.x) | (jid.x == fid.y) | (jid.x == fid.z)
                               | (jid.y == fid.x) | (jid.y == fid.y) | (jid.y == fid.z)
                               | (jid.z == fid.x) | (jid.z == fid.y) | (jid.z == fid.z);
                    v = !share;
                }
            }
            unsigned m = __ballot_sync(0xffffffffu, v);
            while (m && found < KMAX) {
                int b = __ffs(m) - 1;
                if (lane == found) myIntr = base + b;
                found++;
                m &= (m - 1);
            }
        }

        if (lane < found) {
            float4 r0 = d_tri4[3 * f + 0];
            float4 r1 = d_tri4[3 * f + 1];
            float4 r2 = d_tri4[3 * f + 2];
            float4 i0 = d_tri4[3 * myIntr + 0];
            float4 i1 = d_tri4[3 * myIntr + 1];
            float4 i2 = d_tri4[3 * myIntr + 2];
            pen += cone_pen(r0, r1, r2, i0, i1, i2)
                 + cone_pen(i0, i1, i2, r0, r1, r2);
        }
    }

    // warp reduce (fixed order -> deterministic)
#pragma unroll
    for (int o = 16; o; o >>= 1)
        pen += __shfl_down_sync(0xffffffffu, pen, o);
    if (lane == 0) s_warp[wid] = pen;
    __syncthreads();
    if (tid == 0) {
        float s = 0.0f;
#pragma unroll
        for (int w = 0; w < WPB; w++) s += s_warp[w];
        d_part[blockIdx.x] = s;
    }

    grid_barrier();

    // ---------------- Phase 3: block 0 deterministic final reduce -----------
    if (blockIdx.x == 0 && tid == 0) {
        float s = 0.0f;
#pragma unroll 4
        for (int i = 0; i < NBLOCKS; i++) s += d_part[i];
        out[0] = s;
    }
}

extern "C" void kernel_launch(void* const* d_in, const int* in_sizes, int n_in,
                              void* d_out, int out_size) {
    const float* verts = (const float*)d_in[0];  // [1,6890,3] float32
    const int*   faces = (const int*)d_in[1];    // [13776*3] int32
    (void)in_sizes; (void)n_in; (void)out_size;

    fused_kernel<<<NBLOCKS, NTHREADS>>>(verts, faces, (float*)d_out);
}